// round 10
// baseline (speedup 1.0000x reference)
#include <cuda_runtime.h>
#include <cuda_fp16.h>
#include <cstdint>
#include <cstddef>

#define B_ 256
#define N_ 256
#define D_ 1024
#define S_ 1024

// ---------------------------------------------------------------------------
// Scratch (device globals — allocations are forbidden)
// ---------------------------------------------------------------------------
__device__ float g_Apart[8][B_ * S_];            // GEMM1 split-K partials
__device__ float g_Mpart[8][B_ * N_];            // GEMM2 split-K partials
__device__ __align__(16) __half g_Mh[B_ * N_];   // hi(M)
__device__ __align__(16) __half g_Ml[B_ * N_];   // lo(M)
__device__ float g_ctx[2][B_ * D_];              // ctx partials per b-half

// ---------------------------------------------------------------------------
// PTX helpers
// ---------------------------------------------------------------------------
__device__ __forceinline__ uint32_t smem_u32(const void* p) {
    uint32_t a;
    asm("{ .reg .u64 t; cvta.to.shared.u64 t, %1; cvt.u32.u64 %0, t; }"
        : "=r"(a) : "l"(p));
    return a;
}
__device__ __forceinline__ void cp16(uint32_t dst, const void* src) {
    asm volatile("cp.async.cg.shared.global [%0], [%1], 16;" :: "r"(dst), "l"(src));
}
#define CP_COMMIT() asm volatile("cp.async.commit_group;" ::: "memory")
#define CP_WAIT0()  asm volatile("cp.async.wait_group 0;" ::: "memory")

__device__ __forceinline__ void ldsm_x4(uint32_t* r, uint32_t addr) {
    asm volatile("ldmatrix.sync.aligned.m8n8.x4.shared.b16 {%0,%1,%2,%3}, [%4];"
                 : "=r"(r[0]), "=r"(r[1]), "=r"(r[2]), "=r"(r[3]) : "r"(addr));
}
__device__ __forceinline__ void ldsm_x4_t(uint32_t* r, uint32_t addr) {
    asm volatile("ldmatrix.sync.aligned.m8n8.x4.trans.shared.b16 {%0,%1,%2,%3}, [%4];"
                 : "=r"(r[0]), "=r"(r[1]), "=r"(r[2]), "=r"(r[3]) : "r"(addr));
}
__device__ __forceinline__ void mma16816(float* c, const uint32_t* a, const uint32_t* b) {
    asm volatile(
        "mma.sync.aligned.m16n8k16.row.col.f32.f16.f16.f32 "
        "{%0,%1,%2,%3}, {%4,%5,%6,%7}, {%8,%9}, {%0,%1,%2,%3};"
        : "+f"(c[0]), "+f"(c[1]), "+f"(c[2]), "+f"(c[3])
        : "r"(a[0]), "r"(a[1]), "r"(a[2]), "r"(a[3]), "r"(b[0]), "r"(b[1]));
}
__device__ __forceinline__ void st_cluster_f32(uint32_t addr, uint32_t rank, float v) {
    asm volatile(
        "{ .reg .b32 ra; mapa.shared::cluster.u32 ra, %0, %1; "
        "st.shared::cluster.f32 [ra], %2; }"
        :: "r"(addr), "r"(rank), "f"(v) : "memory");
}
#define CLUSTER_ARV()  asm volatile("barrier.cluster.arrive.aligned;" ::: "memory")
#define CLUSTER_WAIT() asm volatile("barrier.cluster.wait.aligned;" ::: "memory")

// ---------------------------------------------------------------------------
// Split-K GEMM 1: g_Apart[kz][m][n] = sum_{k slice} state[m][k] * Q[n][k]
// ---------------------------------------------------------------------------
__global__ void gemm_nt_sk(const float* __restrict__ A,
                           const float* __restrict__ Bm) {
    __shared__ float As[16][64];
    __shared__ float Bs[16][64];
    const int m0 = blockIdx.y * 64, n0 = blockIdx.x * 64;
    const int kz = blockIdx.z;
    const int kbase = kz * 128;
    const int t = threadIdx.x;
    const int tx = t % 16, ty = t / 16;
    const int lk = t % 16, lr = t / 16;
    float acc[4][4] = {};
    for (int k0 = kbase; k0 < kbase + 128; k0 += 16) {
#pragma unroll
        for (int j = 0; j < 4; j++) {
            As[lk][lr + 16 * j] = A[(size_t)(m0 + lr + 16 * j) * S_ + k0 + lk];
            Bs[lk][lr + 16 * j] = Bm[(size_t)(n0 + lr + 16 * j) * S_ + k0 + lk];
        }
        __syncthreads();
#pragma unroll
        for (int k = 0; k < 16; k++) {
            float a[4], b[4];
#pragma unroll
            for (int x = 0; x < 4; x++) a[x] = As[k][ty + 16 * x];
#pragma unroll
            for (int y = 0; y < 4; y++) b[y] = Bs[k][tx + 16 * y];
#pragma unroll
            for (int x = 0; x < 4; x++)
#pragma unroll
                for (int y = 0; y < 4; y++) acc[x][y] = fmaf(a[x], b[y], acc[x][y]);
        }
        __syncthreads();
    }
#pragma unroll
    for (int x = 0; x < 4; x++)
#pragma unroll
        for (int y = 0; y < 4; y++)
            g_Apart[kz][(size_t)(m0 + ty + 16 * x) * S_ + n0 + tx + 16 * y] =
                acc[x][y];
}

// ---------------------------------------------------------------------------
// Split-K GEMM 2: g_Mpart[kz][m][n] = sum_{k slice} A[m][k] * Kmat[k][n]
// ---------------------------------------------------------------------------
__global__ void gemm_nn_sk(const float* __restrict__ Bm) {
    __shared__ float As[16][64];
    __shared__ float Bs[16][64];
    const int m0 = blockIdx.y * 64, n0 = blockIdx.x * 64;
    const int kz = blockIdx.z;
    const int kbase = kz * 128;
    const int t = threadIdx.x;
    const int tx = t % 16, ty = t / 16;
    const int lk = t % 16, lr = t / 16;
    const int bk = t / 64, bn = t % 64;
    float acc[4][4] = {};
    for (int k0 = kbase; k0 < kbase + 128; k0 += 16) {
#pragma unroll
        for (int j = 0; j < 4; j++) {
            size_t idx = (size_t)(m0 + lr + 16 * j) * S_ + k0 + lk;
            float s = 0.f;
#pragma unroll
            for (int p = 0; p < 8; p++) s += g_Apart[p][idx];
            As[lk][lr + 16 * j] = s;
        }
#pragma unroll
        for (int j = 0; j < 4; j++)
            Bs[bk + 4 * j][bn] = Bm[(size_t)(k0 + bk + 4 * j) * N_ + n0 + bn];
        __syncthreads();
#pragma unroll
        for (int k = 0; k < 16; k++) {
            float a[4], b[4];
#pragma unroll
            for (int x = 0; x < 4; x++) a[x] = As[k][ty + 16 * x];
#pragma unroll
            for (int y = 0; y < 4; y++) b[y] = Bs[k][tx + 16 * y];
#pragma unroll
            for (int x = 0; x < 4; x++)
#pragma unroll
                for (int y = 0; y < 4; y++) acc[x][y] = fmaf(a[x], b[y], acc[x][y]);
        }
        __syncthreads();
    }
#pragma unroll
    for (int x = 0; x < 4; x++)
#pragma unroll
        for (int y = 0; y < 4; y++)
            g_Mpart[kz][(size_t)(m0 + ty + 16 * x) * N_ + n0 + tx + 16 * y] =
                acc[x][y];
}

// ---------------------------------------------------------------------------
// convert M: sum 8 partials -> fp16 hi/lo
// ---------------------------------------------------------------------------
__global__ void convert_M() {
    int idx = blockIdx.x * blockDim.x + threadIdx.x;
    float v = 0.f;
#pragma unroll
    for (int p = 0; p < 8; p++) v += g_Mpart[p][idx];
    __half h = __float2half_rn(v);
    __half l = __float2half_rn(v - __half2float(h));
    g_Mh[idx] = h;
    g_Ml[idx] = l;
}

// ---------------------------------------------------------------------------
// Fused (R7 structure): logits GEMM (fp16 3-way split, in-loop B convert)
//        + SINGLE-exchange cluster softmax + W + ctx partials
// grid (8, 2, 256): x = d-slice (cluster 8), y = b-half, z = i.
// CTA tile m=128(b) x n=128(d), K=256 (n) in 8 chunks of 32. 2 CTAs/SM.
// ---------------------------------------------------------------------------
#define SA_OFF   0
#define SA_STAGE 20480   // hi 128*80 + lo 128*80
#define SA_HL    10240
#define SA_PITCH 80
#define SB_OFF   40960
#define SB_STAGE 17408   // hi 32*272 + lo 32*272
#define SB_HL    8704
#define SB_PITCH 272
#define RED_OFF   75776  // float[128][2]
#define RED1_OFF  76800  // float[8][128]  cluster mloc
#define RED2_OFF  80896  // float[8][128]  cluster sloc
#define GV_OFF    84992  // float[128]     CTA-local max
#define INV_OFF   85504  // float[128]     final scale
#define CTXR_OFF  86016  // float[4][128]
#define SMEM_DYN  88064

__global__ void __cluster_dims__(8, 1, 1) __launch_bounds__(256, 2)
fused_attn(const float* __restrict__ FV, float* __restrict__ out) {
    extern __shared__ char smem[];
    const uint32_t sbase = smem_u32(smem);
    const int tid = threadIdx.x;
    const int lane = tid & 31, w = tid >> 5;
    const int i = blockIdx.z;
    const int bhalf = blockIdx.y;
    const int b0 = bhalf * 128;
    const int rank = blockIdx.x;
    const int d0 = rank * 128;
    const float* fvB = FV + (size_t)i * N_ * D_ + d0;                    // n-indexed
    const float* fvC = FV + (size_t)i * N_ * D_ + (size_t)b0 * D_ + d0;  // b-indexed

    float acc[2][8][4];
#pragma unroll
    for (int a = 0; a < 2; a++)
#pragma unroll
        for (int b = 0; b < 8; b++)
#pragma unroll
            for (int c = 0; c < 4; c++) acc[a][b][c] = 0.f;

    // A: threads 0-127 hi, 128-255 lo; one b-row (64B) x4 cp16
    const int ahl = tid >> 7;
    const int arow = tid & 127;
    const char* asrc = ahl ? (const char*)g_Ml : (const char*)g_Mh;
    auto loadA = [&](int c, int s) {
        uint32_t dst0 = sbase + SA_OFF + s * SA_STAGE + ahl * SA_HL + arow * SA_PITCH;
        const char* src = asrc + (size_t)(b0 + arow) * 512 + c * 64;
#pragma unroll
        for (int q = 0; q < 4; q++) cp16(dst0 + q * 16, src + q * 16);
        CP_COMMIT();
    };

    // B: chunk = 32 n-rows x 128 floats; 256 threads x 4 float4 (LDG prefetch)
    const int rk = tid >> 3;
    const int jb = (tid & 7) * 4;
    float4 bf[4];
    auto loadB = [&](int c) {
        const float4* src = (const float4*)(fvB + (size_t)(c * 32 + rk) * D_);
#pragma unroll
        for (int it = 0; it < 4; it++) bf[it] = src[(jb >> 2) + it * 8];
    };

    loadA(0, 0);
    loadB(0);

    const int m0w = (w >> 1) * 32;
    const int n0w = (w & 1) * 64;
    const int kofB = (lane & 7) | (((lane >> 3) & 1) << 3);
    const int nofB = (lane >> 4) * 8;

#pragma unroll 1
    for (int c = 0; c < 8; c++) {
        const int s = c & 1;
        CP_WAIT0();
        __syncthreads();
        if (c < 7) loadA(c + 1, (c + 1) & 1);

        {
            char* sbb = smem + SB_OFF + s * SB_STAGE + rk * SB_PITCH;
#pragma unroll
            for (int it = 0; it < 4; it++) {
                float4 v = bf[it];
                int j = jb + it * 32;
                __half hx = __float2half_rn(v.x), hy = __float2half_rn(v.y);
                __half hz = __float2half_rn(v.z), hw = __float2half_rn(v.w);
                __half2 p0 = __halves2half2(hx, hy), p1 = __halves2half2(hz, hw);
                uint2 hiw = make_uint2(*(uint32_t*)&p0, *(uint32_t*)&p1);
                __half lx = __float2half_rn(v.x - __half2float(hx));
                __half ly = __float2half_rn(v.y - __half2float(hy));
                __half lz = __float2half_rn(v.z - __half2float(hz));
                __half lw = __float2half_rn(v.w - __half2float(hw));
                __half2 q0 = __halves2half2(lx, ly), q1 = __halves2half2(lz, lw);
                uint2 low = make_uint2(*(uint32_t*)&q0, *(uint32_t*)&q1);
                *(uint2*)(sbb + j * 2) = hiw;
                *(uint2*)(sbb + SB_HL + j * 2) = low;
            }
        }
        if (c < 7) loadB(c + 1);
        __syncthreads();

        const uint32_t sa_h = sbase + SA_OFF + s * SA_STAGE;
        const uint32_t sb_h = sbase + SB_OFF + s * SB_STAGE;
        const uint32_t aBase = sa_h + (m0w + (lane & 15)) * SA_PITCH + (lane >> 4) * 16;

#pragma unroll
        for (int ks = 0; ks < 2; ks++) {
            uint32_t aH[2][4], aL[2][4];
#pragma unroll
            for (int mf = 0; mf < 2; mf++) {
                uint32_t ad = aBase + mf * (16 * SA_PITCH) + ks * 32;
                ldsm_x4(aH[mf], ad);
                ldsm_x4(aL[mf], ad + SA_HL);
            }
#pragma unroll
            for (int nf2 = 0; nf2 < 4; nf2++) {
                uint32_t bad = sb_h + (ks * 16 + kofB) * SB_PITCH +
                               (n0w + nf2 * 16 + nofB) * 2;
                uint32_t bh[4], bl[4];
                ldsm_x4_t(bh, bad);
                ldsm_x4_t(bl, bad + SB_HL);
#pragma unroll
                for (int mf = 0; mf < 2; mf++) {
                    mma16816(acc[mf][2 * nf2],     aH[mf], bh);
                    mma16816(acc[mf][2 * nf2 + 1], aH[mf], bh + 2);
                    mma16816(acc[mf][2 * nf2],     aH[mf], bl);
                    mma16816(acc[mf][2 * nf2 + 1], aH[mf], bl + 2);
                    mma16816(acc[mf][2 * nf2],     aL[mf], bh);
                    mma16816(acc[mf][2 * nf2 + 1], aL[mf], bh + 2);
                }
            }
        }
    }

    // -------- single-exchange softmax epilogue (flash rescaling) --------
    float* red  = (float*)(smem + RED_OFF);
    float* red1 = (float*)(smem + RED1_OFF);   // mloc from all ranks
    float* red2 = (float*)(smem + RED2_OFF);   // sloc from all ranks
    float* gv   = (float*)(smem + GV_OFF);     // CTA-local max
    float* inv  = (float*)(smem + INV_OFF);    // final scale
    float* ctxr = (float*)(smem + CTXR_OFF);
    __syncthreads();

    // CTA-local row max
    float rmax[2][2];
#pragma unroll
    for (int mf = 0; mf < 2; mf++)
#pragma unroll
        for (int h = 0; h < 2; h++) {
            float m = -1e30f;
#pragma unroll
            for (int nf = 0; nf < 8; nf++)
                m = fmaxf(m, fmaxf(acc[mf][nf][2 * h], acc[mf][nf][2 * h + 1]));
            m = fmaxf(m, __shfl_xor_sync(0xffffffffu, m, 1));
            m = fmaxf(m, __shfl_xor_sync(0xffffffffu, m, 2));
            rmax[mf][h] = m;
        }
    if ((lane & 3) == 0) {
#pragma unroll
        for (int mf = 0; mf < 2; mf++)
#pragma unroll
            for (int h = 0; h < 2; h++) {
                int row = m0w + mf * 16 + (lane >> 2) + 8 * h;
                red[row * 2 + (w & 1)] = rmax[mf][h];
            }
    }
    __syncthreads();
    if (tid < 128) gv[tid] = fmaxf(red[tid * 2], red[tid * 2 + 1]);
    __syncthreads();

    // exp against local max + local row sum
    float rsum[2][2];
#pragma unroll
    for (int mf = 0; mf < 2; mf++)
#pragma unroll
        for (int h = 0; h < 2; h++) {
            int row = m0w + mf * 16 + (lane >> 2) + 8 * h;
            float gm = gv[row];
            float s = 0.f;
#pragma unroll
            for (int nf = 0; nf < 8; nf++) {
                float e0 = __expf(acc[mf][nf][2 * h] - gm);
                float e1 = __expf(acc[mf][nf][2 * h + 1] - gm);
                acc[mf][nf][2 * h] = e0;
                acc[mf][nf][2 * h + 1] = e1;
                s += e0 + e1;
            }
            s += __shfl_xor_sync(0xffffffffu, s, 1);
            s += __shfl_xor_sync(0xffffffffu, s, 2);
            rsum[mf][h] = s;
        }
    if ((lane & 3) == 0) {
#pragma unroll
        for (int mf = 0; mf < 2; mf++)
#pragma unroll
            for (int h = 0; h < 2; h++) {
                int row = m0w + mf * 16 + (lane >> 2) + 8 * h;
                red[row * 2 + (w & 1)] = rsum[mf][h];
            }
    }
    __syncthreads();

    // ONE cluster exchange of (mloc, sloc)
    if (tid < 128) {
        float mloc = gv[tid];
        float sloc = red[tid * 2] + red[tid * 2 + 1];
        const uint32_t a1 = sbase + RED1_OFF + (rank * 128 + tid) * 4;
        const uint32_t a2 = sbase + RED2_OFF + (rank * 128 + tid) * 4;
#pragma unroll
        for (int p = 0; p < 8; p++) {
            st_cluster_f32(a1, p, mloc);
            st_cluster_f32(a2, p, sloc);
        }
    }
    CLUSTER_ARV(); CLUSTER_WAIT();
    if (tid < 128) {
        float gm = -1e30f;
#pragma unroll
        for (int p = 0; p < 8; p++) gm = fmaxf(gm, red1[p * 128 + tid]);
        float gs = 0.f;
#pragma unroll
        for (int p = 0; p < 8; p++)
            gs += red2[p * 128 + tid] * __expf(red1[p * 128 + tid] - gm);
        inv[tid] = __expf(gv[tid] - gm) * __frcp_rn(gs);
    }
    __syncthreads();

    // W write + ctx partial (b-indexed FV)
    float* Wout = out + (size_t)B_ * D_ + (size_t)i * N_ * D_ + (size_t)b0 * D_ + d0;
    float ctxc[16];
#pragma unroll
    for (int j = 0; j < 16; j++) ctxc[j] = 0.f;

#pragma unroll
    for (int mf = 0; mf < 2; mf++)
#pragma unroll
        for (int h = 0; h < 2; h++) {
            int row = m0w + mf * 16 + (lane >> 2) + 8 * h;
            float iv = inv[row];
            const float* fvr = fvC + (size_t)row * D_;
            float* wr = Wout + (size_t)row * D_;
#pragma unroll
            for (int nf = 0; nf < 8; nf++) {
                int col = n0w + nf * 8 + (lane & 3) * 2;
                float w0 = acc[mf][nf][2 * h] * iv;
                float w1 = acc[mf][nf][2 * h + 1] * iv;
                *(float2*)(wr + col) = make_float2(w0, w1);
                float2 f = *(const float2*)(fvr + col);
                ctxc[nf * 2]     = fmaf(w0, f.x, ctxc[nf * 2]);
                ctxc[nf * 2 + 1] = fmaf(w1, f.y, ctxc[nf * 2 + 1]);
            }
        }
#pragma unroll
    for (int j = 0; j < 16; j++) {
        ctxc[j] += __shfl_xor_sync(0xffffffffu, ctxc[j], 4);
        ctxc[j] += __shfl_xor_sync(0xffffffffu, ctxc[j], 8);
        ctxc[j] += __shfl_xor_sync(0xffffffffu, ctxc[j], 16);
    }
    if (lane < 4) {
#pragma unroll
        for (int nf = 0; nf < 8; nf++) {
            int col = n0w + nf * 8 + lane * 2;
            ctxr[(w >> 1) * 128 + col]     = ctxc[nf * 2];
            ctxr[(w >> 1) * 128 + col + 1] = ctxc[nf * 2 + 1];
        }
    }
    __syncthreads();
    if (tid < 128) {
        float s = 0.f;
#pragma unroll
        for (int p = 0; p < 4; p++) s += ctxr[p * 128 + tid];
        g_ctx[bhalf][(size_t)i * D_ + d0 + tid] = s;
    }
}

// ---------------------------------------------------------------------------
// final: out_ctx[i][d] = g_ctx[0][i][d] + g_ctx[1][i][d]
// ---------------------------------------------------------------------------
__global__ void ctx_reduce(float* __restrict__ out) {
    int idx = blockIdx.x * blockDim.x + threadIdx.x;
    const float4* a = (const float4*)g_ctx[0];
    const float4* b = (const float4*)g_ctx[1];
    float4 va = a[idx], vb = b[idx];
    ((float4*)out)[idx] = make_float4(va.x + vb.x, va.y + vb.y,
                                      va.z + vb.z, va.w + vb.w);
}

// ---------------------------------------------------------------------------
extern "C" void kernel_launch(void* const* d_in, const int* in_sizes, int n_in,
                              void* d_out, int out_size) {
    const float* FV    = (const float*)d_in[0];
    const float* state = (const float*)d_in[1];
    const float* Q     = (const float*)d_in[2];
    const float* Kmat  = (const float*)d_in[3];
    float* out = (float*)d_out;

    cudaFuncSetAttribute(fused_attn, cudaFuncAttributeMaxDynamicSharedMemorySize,
                         SMEM_DYN);

    gemm_nt_sk<<<dim3(S_ / 64, B_ / 64, 8), 256>>>(state, Q);
    gemm_nn_sk<<<dim3(N_ / 64, B_ / 64, 8), 256>>>(Kmat);
    convert_M<<<(B_ * N_) / 256, 256>>>();
    fused_attn<<<dim3(8, 2, B_), 256, SMEM_DYN>>>(FV, out);
    ctx_reduce<<<(B_ * D_ / 4) / 256, 256>>>(out);
}

// round 11
// speedup vs baseline: 1.5017x; 1.5017x over previous
#include <cuda_runtime.h>
#include <cuda_fp16.h>
#include <cstdint>
#include <cstddef>

#define B_ 256
#define N_ 256
#define D_ 1024
#define S_ 1024

// ---------------------------------------------------------------------------
// Scratch (device globals — allocations are forbidden)
// ---------------------------------------------------------------------------
__device__ float g_Apart[8][B_ * S_];            // GEMM1 split-K partials
__device__ float g_Mpart[8][B_ * N_];            // GEMM2 split-K partials
__device__ __align__(16) __half g_Mh[B_ * N_];   // hi(M)
__device__ __align__(16) __half g_Ml[B_ * N_];   // lo(M)
__device__ float g_ctx[2][B_ * D_];              // ctx partials per b-half

// ---------------------------------------------------------------------------
// PTX helpers
// ---------------------------------------------------------------------------
__device__ __forceinline__ uint32_t smem_u32(const void* p) {
    uint32_t a;
    asm("{ .reg .u64 t; cvta.to.shared.u64 t, %1; cvt.u32.u64 %0, t; }"
        : "=r"(a) : "l"(p));
    return a;
}
__device__ __forceinline__ void cp16(uint32_t dst, const void* src) {
    asm volatile("cp.async.cg.shared.global [%0], [%1], 16;" :: "r"(dst), "l"(src));
}
#define CP_COMMIT() asm volatile("cp.async.commit_group;" ::: "memory")
#define CP_WAIT0()  asm volatile("cp.async.wait_group 0;" ::: "memory")

__device__ __forceinline__ void ldsm_x4(uint32_t* r, uint32_t addr) {
    asm volatile("ldmatrix.sync.aligned.m8n8.x4.shared.b16 {%0,%1,%2,%3}, [%4];"
                 : "=r"(r[0]), "=r"(r[1]), "=r"(r[2]), "=r"(r[3]) : "r"(addr));
}
__device__ __forceinline__ void ldsm_x4_t(uint32_t* r, uint32_t addr) {
    asm volatile("ldmatrix.sync.aligned.m8n8.x4.trans.shared.b16 {%0,%1,%2,%3}, [%4];"
                 : "=r"(r[0]), "=r"(r[1]), "=r"(r[2]), "=r"(r[3]) : "r"(addr));
}
__device__ __forceinline__ void mma16816(float* c, const uint32_t* a, const uint32_t* b) {
    asm volatile(
        "mma.sync.aligned.m16n8k16.row.col.f32.f16.f16.f32 "
        "{%0,%1,%2,%3}, {%4,%5,%6,%7}, {%8,%9}, {%0,%1,%2,%3};"
        : "+f"(c[0]), "+f"(c[1]), "+f"(c[2]), "+f"(c[3])
        : "r"(a[0]), "r"(a[1]), "r"(a[2]), "r"(a[3]), "r"(b[0]), "r"(b[1]));
}
__device__ __forceinline__ void st_cluster_f32(uint32_t addr, uint32_t rank, float v) {
    asm volatile(
        "{ .reg .b32 ra; mapa.shared::cluster.u32 ra, %0, %1; "
        "st.shared::cluster.f32 [ra], %2; }"
        :: "r"(addr), "r"(rank), "f"(v) : "memory");
}
#define CLUSTER_ARV()  asm volatile("barrier.cluster.arrive.aligned;" ::: "memory")
#define CLUSTER_WAIT() asm volatile("barrier.cluster.wait.aligned;" ::: "memory")

// ---------------------------------------------------------------------------
// Split-K GEMM 1: g_Apart[kz][m][n] = sum_{k slice} state[m][k] * Q[n][k]
// ---------------------------------------------------------------------------
__global__ void gemm_nt_sk(const float* __restrict__ A,
                           const float* __restrict__ Bm) {
    __shared__ float As[16][64];
    __shared__ float Bs[16][64];
    const int m0 = blockIdx.y * 64, n0 = blockIdx.x * 64;
    const int kz = blockIdx.z;
    const int kbase = kz * 128;
    const int t = threadIdx.x;
    const int tx = t % 16, ty = t / 16;
    const int lk = t % 16, lr = t / 16;
    float acc[4][4] = {};
    for (int k0 = kbase; k0 < kbase + 128; k0 += 16) {
#pragma unroll
        for (int j = 0; j < 4; j++) {
            As[lk][lr + 16 * j] = A[(size_t)(m0 + lr + 16 * j) * S_ + k0 + lk];
            Bs[lk][lr + 16 * j] = Bm[(size_t)(n0 + lr + 16 * j) * S_ + k0 + lk];
        }
        __syncthreads();
#pragma unroll
        for (int k = 0; k < 16; k++) {
            float a[4], b[4];
#pragma unroll
            for (int x = 0; x < 4; x++) a[x] = As[k][ty + 16 * x];
#pragma unroll
            for (int y = 0; y < 4; y++) b[y] = Bs[k][tx + 16 * y];
#pragma unroll
            for (int x = 0; x < 4; x++)
#pragma unroll
                for (int y = 0; y < 4; y++) acc[x][y] = fmaf(a[x], b[y], acc[x][y]);
        }
        __syncthreads();
    }
#pragma unroll
    for (int x = 0; x < 4; x++)
#pragma unroll
        for (int y = 0; y < 4; y++)
            g_Apart[kz][(size_t)(m0 + ty + 16 * x) * S_ + n0 + tx + 16 * y] =
                acc[x][y];
}

// ---------------------------------------------------------------------------
// Split-K GEMM 2: g_Mpart[kz][m][n] = sum_{k slice} A[m][k] * Kmat[k][n]
// ---------------------------------------------------------------------------
__global__ void gemm_nn_sk(const float* __restrict__ Bm) {
    __shared__ float As[16][64];
    __shared__ float Bs[16][64];
    const int m0 = blockIdx.y * 64, n0 = blockIdx.x * 64;
    const int kz = blockIdx.z;
    const int kbase = kz * 128;
    const int t = threadIdx.x;
    const int tx = t % 16, ty = t / 16;
    const int lk = t % 16, lr = t / 16;
    const int bk = t / 64, bn = t % 64;
    float acc[4][4] = {};
    for (int k0 = kbase; k0 < kbase + 128; k0 += 16) {
#pragma unroll
        for (int j = 0; j < 4; j++) {
            size_t idx = (size_t)(m0 + lr + 16 * j) * S_ + k0 + lk;
            float s = 0.f;
#pragma unroll
            for (int p = 0; p < 8; p++) s += g_Apart[p][idx];
            As[lk][lr + 16 * j] = s;
        }
#pragma unroll
        for (int j = 0; j < 4; j++)
            Bs[bk + 4 * j][bn] = Bm[(size_t)(k0 + bk + 4 * j) * N_ + n0 + bn];
        __syncthreads();
#pragma unroll
        for (int k = 0; k < 16; k++) {
            float a[4], b[4];
#pragma unroll
            for (int x = 0; x < 4; x++) a[x] = As[k][ty + 16 * x];
#pragma unroll
            for (int y = 0; y < 4; y++) b[y] = Bs[k][tx + 16 * y];
#pragma unroll
            for (int x = 0; x < 4; x++)
#pragma unroll
                for (int y = 0; y < 4; y++) acc[x][y] = fmaf(a[x], b[y], acc[x][y]);
        }
        __syncthreads();
    }
#pragma unroll
    for (int x = 0; x < 4; x++)
#pragma unroll
        for (int y = 0; y < 4; y++)
            g_Mpart[kz][(size_t)(m0 + ty + 16 * x) * N_ + n0 + tx + 16 * y] =
                acc[x][y];
}

// ---------------------------------------------------------------------------
// convert M: sum 8 partials -> fp16 hi/lo
// ---------------------------------------------------------------------------
__global__ void convert_M() {
    int idx = blockIdx.x * blockDim.x + threadIdx.x;
    float v = 0.f;
#pragma unroll
    for (int p = 0; p < 8; p++) v += g_Mpart[p][idx];
    __half h = __float2half_rn(v);
    __half l = __float2half_rn(v - __half2float(h));
    g_Mh[idx] = h;
    g_Ml[idx] = l;
}

// ---------------------------------------------------------------------------
// Fused (R7-exact): logits GEMM (fp16 3-way split, in-loop B convert)
//        + TWO-exchange cluster softmax + W + ctx partials
// grid (8, 2, 256): x = d-slice (cluster 8), y = b-half, z = i.
// CTA tile m=128(b) x n=128(d), K=256 (n) in 8 chunks of 32. 2 CTAs/SM.
// ---------------------------------------------------------------------------
#define SA_OFF   0
#define SA_STAGE 20480   // hi 128*80 + lo 128*80
#define SA_HL    10240
#define SA_PITCH 80
#define SB_OFF   40960
#define SB_STAGE 17408   // hi 32*272 + lo 32*272
#define SB_HL    8704
#define SB_PITCH 272
#define RED_OFF   75776  // float[128][2]
#define RED1_OFF  76800  // float[8][128]
#define RED2_OFF  80896  // float[8][128]
#define GV_OFF    84992  // float[128]
#define INV_OFF   85504  // float[128]
#define CTXR_OFF  86016  // float[4][128]
#define SMEM_DYN  88064

__global__ void __cluster_dims__(8, 1, 1) __launch_bounds__(256, 2)
fused_attn(const float* __restrict__ FV, float* __restrict__ out) {
    extern __shared__ char smem[];
    const uint32_t sbase = smem_u32(smem);
    const int tid = threadIdx.x;
    const int lane = tid & 31, w = tid >> 5;
    const int i = blockIdx.z;
    const int bhalf = blockIdx.y;
    const int b0 = bhalf * 128;
    const int rank = blockIdx.x;
    const int d0 = rank * 128;
    const float* fvB = FV + (size_t)i * N_ * D_ + d0;                    // n-indexed
    const float* fvC = FV + (size_t)i * N_ * D_ + (size_t)b0 * D_ + d0;  // b-indexed

    float acc[2][8][4];
#pragma unroll
    for (int a = 0; a < 2; a++)
#pragma unroll
        for (int b = 0; b < 8; b++)
#pragma unroll
            for (int c = 0; c < 4; c++) acc[a][b][c] = 0.f;

    // A: threads 0-127 hi, 128-255 lo; one b-row (64B) x4 cp16
    const int ahl = tid >> 7;
    const int arow = tid & 127;
    const char* asrc = ahl ? (const char*)g_Ml : (const char*)g_Mh;
    auto loadA = [&](int c, int s) {
        uint32_t dst0 = sbase + SA_OFF + s * SA_STAGE + ahl * SA_HL + arow * SA_PITCH;
        const char* src = asrc + (size_t)(b0 + arow) * 512 + c * 64;
#pragma unroll
        for (int q = 0; q < 4; q++) cp16(dst0 + q * 16, src + q * 16);
        CP_COMMIT();
    };

    // B: chunk = 32 n-rows x 128 floats; 256 threads x 4 float4 (LDG prefetch)
    const int rk = tid >> 3;
    const int jb = (tid & 7) * 4;
    float4 bf[4];
    auto loadB = [&](int c) {
        const float4* src = (const float4*)(fvB + (size_t)(c * 32 + rk) * D_);
#pragma unroll
        for (int it = 0; it < 4; it++) bf[it] = src[(jb >> 2) + it * 8];
    };

    loadA(0, 0);
    loadB(0);

    const int m0w = (w >> 1) * 32;
    const int n0w = (w & 1) * 64;
    const int kofB = (lane & 7) | (((lane >> 3) & 1) << 3);
    const int nofB = (lane >> 4) * 8;

#pragma unroll 1
    for (int c = 0; c < 8; c++) {
        const int s = c & 1;
        CP_WAIT0();
        __syncthreads();
        if (c < 7) loadA(c + 1, (c + 1) & 1);

        {
            char* sbb = smem + SB_OFF + s * SB_STAGE + rk * SB_PITCH;
#pragma unroll
            for (int it = 0; it < 4; it++) {
                float4 v = bf[it];
                int j = jb + it * 32;
                __half hx = __float2half_rn(v.x), hy = __float2half_rn(v.y);
                __half hz = __float2half_rn(v.z), hw = __float2half_rn(v.w);
                __half2 p0 = __halves2half2(hx, hy), p1 = __halves2half2(hz, hw);
                uint2 hiw = make_uint2(*(uint32_t*)&p0, *(uint32_t*)&p1);
                __half lx = __float2half_rn(v.x - __half2float(hx));
                __half ly = __float2half_rn(v.y - __half2float(hy));
                __half lz = __float2half_rn(v.z - __half2float(hz));
                __half lw = __float2half_rn(v.w - __half2float(hw));
                __half2 q0 = __halves2half2(lx, ly), q1 = __halves2half2(lz, lw);
                uint2 low = make_uint2(*(uint32_t*)&q0, *(uint32_t*)&q1);
                *(uint2*)(sbb + j * 2) = hiw;
                *(uint2*)(sbb + SB_HL + j * 2) = low;
            }
        }
        if (c < 7) loadB(c + 1);
        __syncthreads();

        const uint32_t sa_h = sbase + SA_OFF + s * SA_STAGE;
        const uint32_t sb_h = sbase + SB_OFF + s * SB_STAGE;
        const uint32_t aBase = sa_h + (m0w + (lane & 15)) * SA_PITCH + (lane >> 4) * 16;

#pragma unroll
        for (int ks = 0; ks < 2; ks++) {
            uint32_t aH[2][4], aL[2][4];
#pragma unroll
            for (int mf = 0; mf < 2; mf++) {
                uint32_t ad = aBase + mf * (16 * SA_PITCH) + ks * 32;
                ldsm_x4(aH[mf], ad);
                ldsm_x4(aL[mf], ad + SA_HL);
            }
#pragma unroll
            for (int nf2 = 0; nf2 < 4; nf2++) {
                uint32_t bad = sb_h + (ks * 16 + kofB) * SB_PITCH +
                               (n0w + nf2 * 16 + nofB) * 2;
                uint32_t bh[4], bl[4];
                ldsm_x4_t(bh, bad);
                ldsm_x4_t(bl, bad + SB_HL);
#pragma unroll
                for (int mf = 0; mf < 2; mf++) {
                    mma16816(acc[mf][2 * nf2],     aH[mf], bh);
                    mma16816(acc[mf][2 * nf2 + 1], aH[mf], bh + 2);
                    mma16816(acc[mf][2 * nf2],     aH[mf], bl);
                    mma16816(acc[mf][2 * nf2 + 1], aH[mf], bl + 2);
                    mma16816(acc[mf][2 * nf2],     aL[mf], bh);
                    mma16816(acc[mf][2 * nf2 + 1], aL[mf], bh + 2);
                }
            }
        }
    }

    // ---------------- R7 two-exchange softmax epilogue ----------------
    float* red  = (float*)(smem + RED_OFF);
    float* red1 = (float*)(smem + RED1_OFF);
    float* red2 = (float*)(smem + RED2_OFF);
    float* gv   = (float*)(smem + GV_OFF);
    float* inv  = (float*)(smem + INV_OFF);
    float* ctxr = (float*)(smem + CTXR_OFF);
    __syncthreads();

    float rmax[2][2];
#pragma unroll
    for (int mf = 0; mf < 2; mf++)
#pragma unroll
        for (int h = 0; h < 2; h++) {
            float m = -1e30f;
#pragma unroll
            for (int nf = 0; nf < 8; nf++)
                m = fmaxf(m, fmaxf(acc[mf][nf][2 * h], acc[mf][nf][2 * h + 1]));
            m = fmaxf(m, __shfl_xor_sync(0xffffffffu, m, 1));
            m = fmaxf(m, __shfl_xor_sync(0xffffffffu, m, 2));
            rmax[mf][h] = m;
        }
    if ((lane & 3) == 0) {
#pragma unroll
        for (int mf = 0; mf < 2; mf++)
#pragma unroll
            for (int h = 0; h < 2; h++) {
                int row = m0w + mf * 16 + (lane >> 2) + 8 * h;
                red[row * 2 + (w & 1)] = rmax[mf][h];
            }
    }
    __syncthreads();
    if (tid < 128) {
        float m = fmaxf(red[tid * 2], red[tid * 2 + 1]);
        const uint32_t a = sbase + RED1_OFF + (rank * 128 + tid) * 4;
#pragma unroll
        for (int p = 0; p < 8; p++) st_cluster_f32(a, p, m);
    }
    CLUSTER_ARV(); CLUSTER_WAIT();
    if (tid < 128) {
        float m = -1e30f;
#pragma unroll
        for (int p = 0; p < 8; p++) m = fmaxf(m, red1[p * 128 + tid]);
        gv[tid] = m;
    }
    __syncthreads();

    float rsum[2][2];
#pragma unroll
    for (int mf = 0; mf < 2; mf++)
#pragma unroll
        for (int h = 0; h < 2; h++) {
            int row = m0w + mf * 16 + (lane >> 2) + 8 * h;
            float gm = gv[row];
            float s = 0.f;
#pragma unroll
            for (int nf = 0; nf < 8; nf++) {
                float e0 = __expf(acc[mf][nf][2 * h] - gm);
                float e1 = __expf(acc[mf][nf][2 * h + 1] - gm);
                acc[mf][nf][2 * h] = e0;
                acc[mf][nf][2 * h + 1] = e1;
                s += e0 + e1;
            }
            s += __shfl_xor_sync(0xffffffffu, s, 1);
            s += __shfl_xor_sync(0xffffffffu, s, 2);
            rsum[mf][h] = s;
        }
    if ((lane & 3) == 0) {
#pragma unroll
        for (int mf = 0; mf < 2; mf++)
#pragma unroll
            for (int h = 0; h < 2; h++) {
                int row = m0w + mf * 16 + (lane >> 2) + 8 * h;
                red[row * 2 + (w & 1)] = rsum[mf][h];
            }
    }
    __syncthreads();
    if (tid < 128) {
        float s = red[tid * 2] + red[tid * 2 + 1];
        const uint32_t a = sbase + RED2_OFF + (rank * 128 + tid) * 4;
#pragma unroll
        for (int p = 0; p < 8; p++) st_cluster_f32(a, p, s);
    }
    CLUSTER_ARV(); CLUSTER_WAIT();
    if (tid < 128) {
        float s = 0.f;
#pragma unroll
        for (int p = 0; p < 8; p++) s += red2[p * 128 + tid];
        inv[tid] = __frcp_rn(s);
    }
    __syncthreads();

    // W write + ctx partial (b-indexed FV)
    float* Wout = out + (size_t)B_ * D_ + (size_t)i * N_ * D_ + (size_t)b0 * D_ + d0;
    float ctxc[16];
#pragma unroll
    for (int j = 0; j < 16; j++) ctxc[j] = 0.f;

#pragma unroll
    for (int mf = 0; mf < 2; mf++)
#pragma unroll
        for (int h = 0; h < 2; h++) {
            int row = m0w + mf * 16 + (lane >> 2) + 8 * h;
            float iv = inv[row];
            const float* fvr = fvC + (size_t)row * D_;
            float* wr = Wout + (size_t)row * D_;
#pragma unroll
            for (int nf = 0; nf < 8; nf++) {
                int col = n0w + nf * 8 + (lane & 3) * 2;
                float w0 = acc[mf][nf][2 * h] * iv;
                float w1 = acc[mf][nf][2 * h + 1] * iv;
                *(float2*)(wr + col) = make_float2(w0, w1);
                float2 f = *(const float2*)(fvr + col);
                ctxc[nf * 2]     = fmaf(w0, f.x, ctxc[nf * 2]);
                ctxc[nf * 2 + 1] = fmaf(w1, f.y, ctxc[nf * 2 + 1]);
            }
        }
#pragma unroll
    for (int j = 0; j < 16; j++) {
        ctxc[j] += __shfl_xor_sync(0xffffffffu, ctxc[j], 4);
        ctxc[j] += __shfl_xor_sync(0xffffffffu, ctxc[j], 8);
        ctxc[j] += __shfl_xor_sync(0xffffffffu, ctxc[j], 16);
    }
    if (lane < 4) {
#pragma unroll
        for (int nf = 0; nf < 8; nf++) {
            int col = n0w + nf * 8 + lane * 2;
            ctxr[(w >> 1) * 128 + col]     = ctxc[nf * 2];
            ctxr[(w >> 1) * 128 + col + 1] = ctxc[nf * 2 + 1];
        }
    }
    __syncthreads();
    if (tid < 128) {
        float s = 0.f;
#pragma unroll
        for (int p = 0; p < 4; p++) s += ctxr[p * 128 + tid];
        g_ctx[bhalf][(size_t)i * D_ + d0 + tid] = s;
    }
}

// ---------------------------------------------------------------------------
// final: out_ctx[i][d] = g_ctx[0][i][d] + g_ctx[1][i][d]
// ---------------------------------------------------------------------------
__global__ void ctx_reduce(float* __restrict__ out) {
    int idx = blockIdx.x * blockDim.x + threadIdx.x;
    const float4* a = (const float4*)g_ctx[0];
    const float4* b = (const float4*)g_ctx[1];
    float4 va = a[idx], vb = b[idx];
    ((float4*)out)[idx] = make_float4(va.x + vb.x, va.y + vb.y,
                                      va.z + vb.z, va.w + vb.w);
}

// ---------------------------------------------------------------------------
extern "C" void kernel_launch(void* const* d_in, const int* in_sizes, int n_in,
                              void* d_out, int out_size) {
    const float* FV    = (const float*)d_in[0];
    const float* state = (const float*)d_in[1];
    const float* Q     = (const float*)d_in[2];
    const float* Kmat  = (const float*)d_in[3];
    float* out = (float*)d_out;

    cudaFuncSetAttribute(fused_attn, cudaFuncAttributeMaxDynamicSharedMemorySize,
                         SMEM_DYN);

    gemm_nt_sk<<<dim3(S_ / 64, B_ / 64, 8), 256>>>(state, Q);
    gemm_nn_sk<<<dim3(N_ / 64, B_ / 64, 8), 256>>>(Kmat);
    convert_M<<<(B_ * N_) / 256, 256>>>();
    fused_attn<<<dim3(8, 2, B_), 256, SMEM_DYN>>>(FV, out);
    ctx_reduce<<<(B_ * D_ / 4) / 256, 256>>>(out);
}

// round 12
// speedup vs baseline: 1.6168x; 1.0767x over previous
#include <cuda_runtime.h>
#include <cuda_fp16.h>
#include <cstdint>
#include <cstddef>

#define B_ 256
#define N_ 256
#define D_ 1024
#define S_ 1024

// ---------------------------------------------------------------------------
// Scratch (device globals — allocations are forbidden)
// ---------------------------------------------------------------------------
__device__ float g_Apart[8][B_ * S_];            // GEMM1 split-K partials
__device__ float g_Mpart[8][B_ * N_];            // GEMM2 split-K partials
__device__ __align__(16) __half g_Mh[B_ * N_];   // hi(M)
__device__ __align__(16) __half g_Ml[B_ * N_];   // lo(M)
__device__ float g_ctx[2][B_ * D_];              // ctx partials per b-half

// ---------------------------------------------------------------------------
// PTX helpers
// ---------------------------------------------------------------------------
__device__ __forceinline__ uint32_t smem_u32(const void* p) {
    uint32_t a;
    asm("{ .reg .u64 t; cvta.to.shared.u64 t, %1; cvt.u32.u64 %0, t; }"
        : "=r"(a) : "l"(p));
    return a;
}
__device__ __forceinline__ void cp16(uint32_t dst, const void* src) {
    asm volatile("cp.async.cg.shared.global [%0], [%1], 16;" :: "r"(dst), "l"(src));
}
#define CP_COMMIT() asm volatile("cp.async.commit_group;" ::: "memory")
#define CP_WAIT0()  asm volatile("cp.async.wait_group 0;" ::: "memory")

__device__ __forceinline__ void ldsm_x4(uint32_t* r, uint32_t addr) {
    asm volatile("ldmatrix.sync.aligned.m8n8.x4.shared.b16 {%0,%1,%2,%3}, [%4];"
                 : "=r"(r[0]), "=r"(r[1]), "=r"(r[2]), "=r"(r[3]) : "r"(addr));
}
__device__ __forceinline__ void ldsm_x4_t(uint32_t* r, uint32_t addr) {
    asm volatile("ldmatrix.sync.aligned.m8n8.x4.trans.shared.b16 {%0,%1,%2,%3}, [%4];"
                 : "=r"(r[0]), "=r"(r[1]), "=r"(r[2]), "=r"(r[3]) : "r"(addr));
}
__device__ __forceinline__ void mma16816(float* c, const uint32_t* a, const uint32_t* b) {
    asm volatile(
        "mma.sync.aligned.m16n8k16.row.col.f32.f16.f16.f32 "
        "{%0,%1,%2,%3}, {%4,%5,%6,%7}, {%8,%9}, {%0,%1,%2,%3};"
        : "+f"(c[0]), "+f"(c[1]), "+f"(c[2]), "+f"(c[3])
        : "r"(a[0]), "r"(a[1]), "r"(a[2]), "r"(a[3]), "r"(b[0]), "r"(b[1]));
}
__device__ __forceinline__ void st_cluster_f32(uint32_t addr, uint32_t rank, float v) {
    asm volatile(
        "{ .reg .b32 ra; mapa.shared::cluster.u32 ra, %0, %1; "
        "st.shared::cluster.f32 [ra], %2; }"
        :: "r"(addr), "r"(rank), "f"(v) : "memory");
}
#define CLUSTER_ARV()  asm volatile("barrier.cluster.arrive.aligned;" ::: "memory")
#define CLUSTER_WAIT() asm volatile("barrier.cluster.wait.aligned;" ::: "memory")

// ---------------------------------------------------------------------------
// Split-K GEMM 1: g_Apart[kz][m][n] = sum_{k slice} state[m][k] * Q[n][k]
// ---------------------------------------------------------------------------
__global__ void gemm_nt_sk(const float* __restrict__ A,
                           const float* __restrict__ Bm) {
    __shared__ float As[16][64];
    __shared__ float Bs[16][64];
    const int m0 = blockIdx.y * 64, n0 = blockIdx.x * 64;
    const int kz = blockIdx.z;
    const int kbase = kz * 128;
    const int t = threadIdx.x;
    const int tx = t % 16, ty = t / 16;
    const int lk = t % 16, lr = t / 16;
    float acc[4][4] = {};
    for (int k0 = kbase; k0 < kbase + 128; k0 += 16) {
#pragma unroll
        for (int j = 0; j < 4; j++) {
            As[lk][lr + 16 * j] = A[(size_t)(m0 + lr + 16 * j) * S_ + k0 + lk];
            Bs[lk][lr + 16 * j] = Bm[(size_t)(n0 + lr + 16 * j) * S_ + k0 + lk];
        }
        __syncthreads();
#pragma unroll
        for (int k = 0; k < 16; k++) {
            float a[4], b[4];
#pragma unroll
            for (int x = 0; x < 4; x++) a[x] = As[k][ty + 16 * x];
#pragma unroll
            for (int y = 0; y < 4; y++) b[y] = Bs[k][tx + 16 * y];
#pragma unroll
            for (int x = 0; x < 4; x++)
#pragma unroll
                for (int y = 0; y < 4; y++) acc[x][y] = fmaf(a[x], b[y], acc[x][y]);
        }
        __syncthreads();
    }
#pragma unroll
    for (int x = 0; x < 4; x++)
#pragma unroll
        for (int y = 0; y < 4; y++)
            g_Apart[kz][(size_t)(m0 + ty + 16 * x) * S_ + n0 + tx + 16 * y] =
                acc[x][y];
}

// ---------------------------------------------------------------------------
// Split-K GEMM 2: g_Mpart[kz][m][n] = sum_{k slice} A[m][k] * Kmat[k][n]
// ---------------------------------------------------------------------------
__global__ void gemm_nn_sk(const float* __restrict__ Bm) {
    __shared__ float As[16][64];
    __shared__ float Bs[16][64];
    const int m0 = blockIdx.y * 64, n0 = blockIdx.x * 64;
    const int kz = blockIdx.z;
    const int kbase = kz * 128;
    const int t = threadIdx.x;
    const int tx = t % 16, ty = t / 16;
    const int lk = t % 16, lr = t / 16;
    const int bk = t / 64, bn = t % 64;
    float acc[4][4] = {};
    for (int k0 = kbase; k0 < kbase + 128; k0 += 16) {
#pragma unroll
        for (int j = 0; j < 4; j++) {
            size_t idx = (size_t)(m0 + lr + 16 * j) * S_ + k0 + lk;
            float s = 0.f;
#pragma unroll
            for (int p = 0; p < 8; p++) s += g_Apart[p][idx];
            As[lk][lr + 16 * j] = s;
        }
#pragma unroll
        for (int j = 0; j < 4; j++)
            Bs[bk + 4 * j][bn] = Bm[(size_t)(k0 + bk + 4 * j) * N_ + n0 + bn];
        __syncthreads();
#pragma unroll
        for (int k = 0; k < 16; k++) {
            float a[4], b[4];
#pragma unroll
            for (int x = 0; x < 4; x++) a[x] = As[k][ty + 16 * x];
#pragma unroll
            for (int y = 0; y < 4; y++) b[y] = Bs[k][tx + 16 * y];
#pragma unroll
            for (int x = 0; x < 4; x++)
#pragma unroll
                for (int y = 0; y < 4; y++) acc[x][y] = fmaf(a[x], b[y], acc[x][y]);
        }
        __syncthreads();
    }
#pragma unroll
    for (int x = 0; x < 4; x++)
#pragma unroll
        for (int y = 0; y < 4; y++)
            g_Mpart[kz][(size_t)(m0 + ty + 16 * x) * N_ + n0 + tx + 16 * y] =
                acc[x][y];
}

// ---------------------------------------------------------------------------
// convert M: sum 8 partials -> fp16 hi/lo
// ---------------------------------------------------------------------------
__global__ void convert_M() {
    int idx = blockIdx.x * blockDim.x + threadIdx.x;
    float v = 0.f;
#pragma unroll
    for (int p = 0; p < 8; p++) v += g_Mpart[p][idx];
    __half h = __float2half_rn(v);
    __half l = __float2half_rn(v - __half2float(h));
    g_Mh[idx] = h;
    g_Ml[idx] = l;
}

// ---------------------------------------------------------------------------
// Fused: logits GEMM (fp16 3-way split) + TWO-exchange cluster softmax
//        + W + ctx partials.
// Single-sync pipelined mainloop: per chunk, one __syncthreads; convert+STS
// of next chunk overlaps other warps' MMA of current chunk.
// grid (8, 2, 256): x = d-slice (cluster 8), y = b-half, z = i.
// ---------------------------------------------------------------------------
#define SA_OFF   0
#define SA_STAGE 20480   // hi 128*80 + lo 128*80
#define SA_HL    10240
#define SA_PITCH 80
#define SB_OFF   40960
#define SB_STAGE 17408   // hi 32*272 + lo 32*272
#define SB_HL    8704
#define SB_PITCH 272
#define RED_OFF   75776  // float[128][2]
#define RED1_OFF  76800  // float[8][128]
#define RED2_OFF  80896  // float[8][128]
#define GV_OFF    84992  // float[128]
#define INV_OFF   85504  // float[128]
#define CTXR_OFF  86016  // float[4][128]
#define SMEM_DYN  88064

__global__ void __cluster_dims__(8, 1, 1) __launch_bounds__(256, 2)
fused_attn(const float* __restrict__ FV, float* __restrict__ out) {
    extern __shared__ char smem[];
    const uint32_t sbase = smem_u32(smem);
    const int tid = threadIdx.x;
    const int lane = tid & 31, w = tid >> 5;
    const int i = blockIdx.z;
    const int bhalf = blockIdx.y;
    const int b0 = bhalf * 128;
    const int rank = blockIdx.x;
    const int d0 = rank * 128;
    const float* fvB = FV + (size_t)i * N_ * D_ + d0;                    // n-indexed
    const float* fvC = FV + (size_t)i * N_ * D_ + (size_t)b0 * D_ + d0;  // b-indexed

    float acc[2][8][4];
#pragma unroll
    for (int a = 0; a < 2; a++)
#pragma unroll
        for (int b = 0; b < 8; b++)
#pragma unroll
            for (int c = 0; c < 4; c++) acc[a][b][c] = 0.f;

    // A: threads 0-127 hi, 128-255 lo; one b-row (64B) x4 cp16
    const int ahl = tid >> 7;
    const int arow = tid & 127;
    const char* asrc = ahl ? (const char*)g_Ml : (const char*)g_Mh;
    auto loadA = [&](int c, int s) {
        uint32_t dst0 = sbase + SA_OFF + s * SA_STAGE + ahl * SA_HL + arow * SA_PITCH;
        const char* src = asrc + (size_t)(b0 + arow) * 512 + c * 64;
#pragma unroll
        for (int q = 0; q < 4; q++) cp16(dst0 + q * 16, src + q * 16);
        CP_COMMIT();
    };

    // B: chunk = 32 n-rows x 128 floats; 256 threads x 4 float4 (LDG prefetch)
    const int rk = tid >> 3;
    const int jb = (tid & 7) * 4;
    float4 bf[4];
    auto loadB = [&](int c) {
        const float4* src = (const float4*)(fvB + (size_t)(c * 32 + rk) * D_);
#pragma unroll
        for (int it = 0; it < 4; it++) bf[it] = src[(jb >> 2) + it * 8];
    };

    // convert bf (fp32) -> fp16 hi/lo, STS into stage s
    auto convB = [&](int s) {
        char* sbb = smem + SB_OFF + s * SB_STAGE + rk * SB_PITCH;
#pragma unroll
        for (int it = 0; it < 4; it++) {
            float4 v = bf[it];
            int j = jb + it * 32;
            __half hx = __float2half_rn(v.x), hy = __float2half_rn(v.y);
            __half hz = __float2half_rn(v.z), hw = __float2half_rn(v.w);
            __half2 p0 = __halves2half2(hx, hy), p1 = __halves2half2(hz, hw);
            uint2 hiw = make_uint2(*(uint32_t*)&p0, *(uint32_t*)&p1);
            __half lx = __float2half_rn(v.x - __half2float(hx));
            __half ly = __float2half_rn(v.y - __half2float(hy));
            __half lz = __float2half_rn(v.z - __half2float(hz));
            __half lw = __float2half_rn(v.w - __half2float(hw));
            __half2 q0 = __halves2half2(lx, ly), q1 = __halves2half2(lz, lw);
            uint2 low = make_uint2(*(uint32_t*)&q0, *(uint32_t*)&q1);
            *(uint2*)(sbb + j * 2) = hiw;
            *(uint2*)(sbb + SB_HL + j * 2) = low;
        }
    };

    // ---- prologue: stage 0 filled (A via cp.async, B via convert) ----
    loadB(0);                // bf = chunk 0
    loadA(0, 0);
    convB(0);                // stage 0 B ready (this thread)
    loadB(1);                // bf = chunk 1
    CP_WAIT0();              // A chunk 0 landed
    __syncthreads();         // stage 0 fully ready for all warps

    const int m0w = (w >> 1) * 32;
    const int n0w = (w & 1) * 64;
    const int kofB = (lane & 7) | (((lane >> 3) & 1) << 3);
    const int nofB = (lane >> 4) * 8;

#pragma unroll 1
    for (int c = 0; c < 8; c++) {
        const int s = c & 1;
        if (c < 7) loadA(c + 1, s ^ 1);   // cp.async overlaps this chunk's MMA

        const uint32_t sa_h = sbase + SA_OFF + s * SA_STAGE;
        const uint32_t sb_h = sbase + SB_OFF + s * SB_STAGE;
        const uint32_t aBase = sa_h + (m0w + (lane & 15)) * SA_PITCH + (lane >> 4) * 16;

#pragma unroll
        for (int ks = 0; ks < 2; ks++) {
            uint32_t aH[2][4], aL[2][4];
#pragma unroll
            for (int mf = 0; mf < 2; mf++) {
                uint32_t ad = aBase + mf * (16 * SA_PITCH) + ks * 32;
                ldsm_x4(aH[mf], ad);
                ldsm_x4(aL[mf], ad + SA_HL);
            }
#pragma unroll
            for (int nf2 = 0; nf2 < 4; nf2++) {
                uint32_t bad = sb_h + (ks * 16 + kofB) * SB_PITCH +
                               (n0w + nf2 * 16 + nofB) * 2;
                uint32_t bh[4], bl[4];
                ldsm_x4_t(bh, bad);
                ldsm_x4_t(bl, bad + SB_HL);
#pragma unroll
                for (int mf = 0; mf < 2; mf++) {
                    mma16816(acc[mf][2 * nf2],     aH[mf], bh);
                    mma16816(acc[mf][2 * nf2 + 1], aH[mf], bh + 2);
                    mma16816(acc[mf][2 * nf2],     aH[mf], bl);
                    mma16816(acc[mf][2 * nf2 + 1], aH[mf], bl + 2);
                    mma16816(acc[mf][2 * nf2],     aL[mf], bh);
                    mma16816(acc[mf][2 * nf2 + 1], aL[mf], bh + 2);
                }
            }
        }

        if (c < 7) {
            convB(s ^ 1);                 // bf holds chunk c+1; overlaps others' MMA
            if (c + 2 < 8) loadB(c + 2);  // prefetch chunk c+2 into bf
            CP_WAIT0();                   // A(c+1) landed (issued before MMA)
            __syncthreads();              // stage s^1 fully ready; stage s free
        }
    }

    // ---------------- R7 two-exchange softmax epilogue ----------------
    float* red  = (float*)(smem + RED_OFF);
    float* red1 = (float*)(smem + RED1_OFF);
    float* red2 = (float*)(smem + RED2_OFF);
    float* gv   = (float*)(smem + GV_OFF);
    float* inv  = (float*)(smem + INV_OFF);
    float* ctxr = (float*)(smem + CTXR_OFF);
    __syncthreads();

    float rmax[2][2];
#pragma unroll
    for (int mf = 0; mf < 2; mf++)
#pragma unroll
        for (int h = 0; h < 2; h++) {
            float m = -1e30f;
#pragma unroll
            for (int nf = 0; nf < 8; nf++)
                m = fmaxf(m, fmaxf(acc[mf][nf][2 * h], acc[mf][nf][2 * h + 1]));
            m = fmaxf(m, __shfl_xor_sync(0xffffffffu, m, 1));
            m = fmaxf(m, __shfl_xor_sync(0xffffffffu, m, 2));
            rmax[mf][h] = m;
        }
    if ((lane & 3) == 0) {
#pragma unroll
        for (int mf = 0; mf < 2; mf++)
#pragma unroll
            for (int h = 0; h < 2; h++) {
                int row = m0w + mf * 16 + (lane >> 2) + 8 * h;
                red[row * 2 + (w & 1)] = rmax[mf][h];
            }
    }
    __syncthreads();
    if (tid < 128) {
        float m = fmaxf(red[tid * 2], red[tid * 2 + 1]);
        const uint32_t a = sbase + RED1_OFF + (rank * 128 + tid) * 4;
#pragma unroll
        for (int p = 0; p < 8; p++) st_cluster_f32(a, p, m);
    }
    CLUSTER_ARV(); CLUSTER_WAIT();
    if (tid < 128) {
        float m = -1e30f;
#pragma unroll
        for (int p = 0; p < 8; p++) m = fmaxf(m, red1[p * 128 + tid]);
        gv[tid] = m;
    }
    __syncthreads();

    float rsum[2][2];
#pragma unroll
    for (int mf = 0; mf < 2; mf++)
#pragma unroll
        for (int h = 0; h < 2; h++) {
            int row = m0w + mf * 16 + (lane >> 2) + 8 * h;
            float gm = gv[row];
            float s = 0.f;
#pragma unroll
            for (int nf = 0; nf < 8; nf++) {
                float e0 = __expf(acc[mf][nf][2 * h] - gm);
                float e1 = __expf(acc[mf][nf][2 * h + 1] - gm);
                acc[mf][nf][2 * h] = e0;
                acc[mf][nf][2 * h + 1] = e1;
                s += e0 + e1;
            }
            s += __shfl_xor_sync(0xffffffffu, s, 1);
            s += __shfl_xor_sync(0xffffffffu, s, 2);
            rsum[mf][h] = s;
        }
    if ((lane & 3) == 0) {
#pragma unroll
        for (int mf = 0; mf < 2; mf++)
#pragma unroll
            for (int h = 0; h < 2; h++) {
                int row = m0w + mf * 16 + (lane >> 2) + 8 * h;
                red[row * 2 + (w & 1)] = rsum[mf][h];
            }
    }
    __syncthreads();
    if (tid < 128) {
        float s = red[tid * 2] + red[tid * 2 + 1];
        const uint32_t a = sbase + RED2_OFF + (rank * 128 + tid) * 4;
#pragma unroll
        for (int p = 0; p < 8; p++) st_cluster_f32(a, p, s);
    }
    CLUSTER_ARV(); CLUSTER_WAIT();
    if (tid < 128) {
        float s = 0.f;
#pragma unroll
        for (int p = 0; p < 8; p++) s += red2[p * 128 + tid];
        inv[tid] = __frcp_rn(s);
    }
    __syncthreads();

    // W write + ctx partial (b-indexed FV)
    float* Wout = out + (size_t)B_ * D_ + (size_t)i * N_ * D_ + (size_t)b0 * D_ + d0;
    float ctxc[16];
#pragma unroll
    for (int j = 0; j < 16; j++) ctxc[j] = 0.f;

#pragma unroll
    for (int mf = 0; mf < 2; mf++)
#pragma unroll
        for (int h = 0; h < 2; h++) {
            int row = m0w + mf * 16 + (lane >> 2) + 8 * h;
            float iv = inv[row];
            const float* fvr = fvC + (size_t)row * D_;
            float* wr = Wout + (size_t)row * D_;
#pragma unroll
            for (int nf = 0; nf < 8; nf++) {
                int col = n0w + nf * 8 + (lane & 3) * 2;
                float w0 = acc[mf][nf][2 * h] * iv;
                float w1 = acc[mf][nf][2 * h + 1] * iv;
                *(float2*)(wr + col) = make_float2(w0, w1);
                float2 f = *(const float2*)(fvr + col);
                ctxc[nf * 2]     = fmaf(w0, f.x, ctxc[nf * 2]);
                ctxc[nf * 2 + 1] = fmaf(w1, f.y, ctxc[nf * 2 + 1]);
            }
        }
#pragma unroll
    for (int j = 0; j < 16; j++) {
        ctxc[j] += __shfl_xor_sync(0xffffffffu, ctxc[j], 4);
        ctxc[j] += __shfl_xor_sync(0xffffffffu, ctxc[j], 8);
        ctxc[j] += __shfl_xor_sync(0xffffffffu, ctxc[j], 16);
    }
    if (lane < 4) {
#pragma unroll
        for (int nf = 0; nf < 8; nf++) {
            int col = n0w + nf * 8 + lane * 2;
            ctxr[(w >> 1) * 128 + col]     = ctxc[nf * 2];
            ctxr[(w >> 1) * 128 + col + 1] = ctxc[nf * 2 + 1];
        }
    }
    __syncthreads();
    if (tid < 128) {
        float s = 0.f;
#pragma unroll
        for (int p = 0; p < 4; p++) s += ctxr[p * 128 + tid];
        g_ctx[bhalf][(size_t)i * D_ + d0 + tid] = s;
    }
}

// ---------------------------------------------------------------------------
// final: out_ctx[i][d] = g_ctx[0][i][d] + g_ctx[1][i][d]
// ---------------------------------------------------------------------------
__global__ void ctx_reduce(float* __restrict__ out) {
    int idx = blockIdx.x * blockDim.x + threadIdx.x;
    const float4* a = (const float4*)g_ctx[0];
    const float4* b = (const float4*)g_ctx[1];
    float4 va = a[idx], vb = b[idx];
    ((float4*)out)[idx] = make_float4(va.x + vb.x, va.y + vb.y,
                                      va.z + vb.z, va.w + vb.w);
}

// ---------------------------------------------------------------------------
extern "C" void kernel_launch(void* const* d_in, const int* in_sizes, int n_in,
                              void* d_out, int out_size) {
    const float* FV    = (const float*)d_in[0];
    const float* state = (const float*)d_in[1];
    const float* Q     = (const float*)d_in[2];
    const float* Kmat  = (const float*)d_in[3];
    float* out = (float*)d_out;

    cudaFuncSetAttribute(fused_attn, cudaFuncAttributeMaxDynamicSharedMemorySize,
                         SMEM_DYN);

    gemm_nt_sk<<<dim3(S_ / 64, B_ / 64, 8), 256>>>(state, Q);
    gemm_nn_sk<<<dim3(N_ / 64, B_ / 64, 8), 256>>>(Kmat);
    convert_M<<<(B_ * N_) / 256, 256>>>();
    fused_attn<<<dim3(8, 2, B_), 256, SMEM_DYN>>>(FV, out);
    ctx_reduce<<<(B_ * D_ / 4) / 256, 256>>>(out);
}

// round 13
// speedup vs baseline: 1.6176x; 1.0005x over previous
#include <cuda_runtime.h>
#include <cuda_fp16.h>
#include <cstdint>
#include <cstddef>

#define B_ 256
#define N_ 256
#define D_ 1024
#define S_ 1024

// ---------------------------------------------------------------------------
// Scratch (device globals — allocations are forbidden)
// ---------------------------------------------------------------------------
__device__ float g_Apart[8][B_ * S_];            // GEMM1 split-K partials
__device__ float g_Mpart[8][B_ * N_];            // GEMM2 split-K partials
__device__ __align__(16) __half g_Mh[B_ * N_];   // hi(M)
__device__ __align__(16) __half g_Ml[B_ * N_];   // lo(M)
__device__ float g_ctx[2][B_ * D_];              // ctx partials per b-half

// ---------------------------------------------------------------------------
// PTX helpers
// ---------------------------------------------------------------------------
__device__ __forceinline__ uint32_t smem_u32(const void* p) {
    uint32_t a;
    asm("{ .reg .u64 t; cvta.to.shared.u64 t, %1; cvt.u32.u64 %0, t; }"
        : "=r"(a) : "l"(p));
    return a;
}
__device__ __forceinline__ void cp16(uint32_t dst, const void* src) {
    asm volatile("cp.async.cg.shared.global [%0], [%1], 16;" :: "r"(dst), "l"(src));
}
#define CP_COMMIT() asm volatile("cp.async.commit_group;" ::: "memory")
#define CP_WAIT0()  asm volatile("cp.async.wait_group 0;" ::: "memory")

__device__ __forceinline__ void ldsm_x4(uint32_t* r, uint32_t addr) {
    asm volatile("ldmatrix.sync.aligned.m8n8.x4.shared.b16 {%0,%1,%2,%3}, [%4];"
                 : "=r"(r[0]), "=r"(r[1]), "=r"(r[2]), "=r"(r[3]) : "r"(addr));
}
__device__ __forceinline__ void ldsm_x4_t(uint32_t* r, uint32_t addr) {
    asm volatile("ldmatrix.sync.aligned.m8n8.x4.trans.shared.b16 {%0,%1,%2,%3}, [%4];"
                 : "=r"(r[0]), "=r"(r[1]), "=r"(r[2]), "=r"(r[3]) : "r"(addr));
}
__device__ __forceinline__ void mma16816(float* c, const uint32_t* a, const uint32_t* b) {
    asm volatile(
        "mma.sync.aligned.m16n8k16.row.col.f32.f16.f16.f32 "
        "{%0,%1,%2,%3}, {%4,%5,%6,%7}, {%8,%9}, {%0,%1,%2,%3};"
        : "+f"(c[0]), "+f"(c[1]), "+f"(c[2]), "+f"(c[3])
        : "r"(a[0]), "r"(a[1]), "r"(a[2]), "r"(a[3]), "r"(b[0]), "r"(b[1]));
}
__device__ __forceinline__ void st_cluster_f32(uint32_t addr, uint32_t rank, float v) {
    asm volatile(
        "{ .reg .b32 ra; mapa.shared::cluster.u32 ra, %0, %1; "
        "st.shared::cluster.f32 [ra], %2; }"
        :: "r"(addr), "r"(rank), "f"(v) : "memory");
}
#define CLUSTER_ARV()  asm volatile("barrier.cluster.arrive.aligned;" ::: "memory")
#define CLUSTER_WAIT() asm volatile("barrier.cluster.wait.aligned;" ::: "memory")

// ---------------------------------------------------------------------------
// Split-K GEMM 1: g_Apart[kz][m][n] = sum_{k slice} state[m][k] * Q[n][k]
// ---------------------------------------------------------------------------
__global__ void gemm_nt_sk(const float* __restrict__ A,
                           const float* __restrict__ Bm) {
    __shared__ float As[16][64];
    __shared__ float Bs[16][64];
    const int m0 = blockIdx.y * 64, n0 = blockIdx.x * 64;
    const int kz = blockIdx.z;
    const int kbase = kz * 128;
    const int t = threadIdx.x;
    const int tx = t % 16, ty = t / 16;
    const int lk = t % 16, lr = t / 16;
    float acc[4][4] = {};
    for (int k0 = kbase; k0 < kbase + 128; k0 += 16) {
#pragma unroll
        for (int j = 0; j < 4; j++) {
            As[lk][lr + 16 * j] = A[(size_t)(m0 + lr + 16 * j) * S_ + k0 + lk];
            Bs[lk][lr + 16 * j] = Bm[(size_t)(n0 + lr + 16 * j) * S_ + k0 + lk];
        }
        __syncthreads();
#pragma unroll
        for (int k = 0; k < 16; k++) {
            float a[4], b[4];
#pragma unroll
            for (int x = 0; x < 4; x++) a[x] = As[k][ty + 16 * x];
#pragma unroll
            for (int y = 0; y < 4; y++) b[y] = Bs[k][tx + 16 * y];
#pragma unroll
            for (int x = 0; x < 4; x++)
#pragma unroll
                for (int y = 0; y < 4; y++) acc[x][y] = fmaf(a[x], b[y], acc[x][y]);
        }
        __syncthreads();
    }
#pragma unroll
    for (int x = 0; x < 4; x++)
#pragma unroll
        for (int y = 0; y < 4; y++)
            g_Apart[kz][(size_t)(m0 + ty + 16 * x) * S_ + n0 + tx + 16 * y] =
                acc[x][y];
}

// ---------------------------------------------------------------------------
// Split-K GEMM 2: g_Mpart[kz][m][n] = sum_{k slice} A[m][k] * Kmat[k][n]
// ---------------------------------------------------------------------------
__global__ void gemm_nn_sk(const float* __restrict__ Bm) {
    __shared__ float As[16][64];
    __shared__ float Bs[16][64];
    const int m0 = blockIdx.y * 64, n0 = blockIdx.x * 64;
    const int kz = blockIdx.z;
    const int kbase = kz * 128;
    const int t = threadIdx.x;
    const int tx = t % 16, ty = t / 16;
    const int lk = t % 16, lr = t / 16;
    const int bk = t / 64, bn = t % 64;
    float acc[4][4] = {};
    for (int k0 = kbase; k0 < kbase + 128; k0 += 16) {
#pragma unroll
        for (int j = 0; j < 4; j++) {
            size_t idx = (size_t)(m0 + lr + 16 * j) * S_ + k0 + lk;
            float s = 0.f;
#pragma unroll
            for (int p = 0; p < 8; p++) s += g_Apart[p][idx];
            As[lk][lr + 16 * j] = s;
        }
#pragma unroll
        for (int j = 0; j < 4; j++)
            Bs[bk + 4 * j][bn] = Bm[(size_t)(k0 + bk + 4 * j) * N_ + n0 + bn];
        __syncthreads();
#pragma unroll
        for (int k = 0; k < 16; k++) {
            float a[4], b[4];
#pragma unroll
            for (int x = 0; x < 4; x++) a[x] = As[k][ty + 16 * x];
#pragma unroll
            for (int y = 0; y < 4; y++) b[y] = Bs[k][tx + 16 * y];
#pragma unroll
            for (int x = 0; x < 4; x++)
#pragma unroll
                for (int y = 0; y < 4; y++) acc[x][y] = fmaf(a[x], b[y], acc[x][y]);
        }
        __syncthreads();
    }
#pragma unroll
    for (int x = 0; x < 4; x++)
#pragma unroll
        for (int y = 0; y < 4; y++)
            g_Mpart[kz][(size_t)(m0 + ty + 16 * x) * N_ + n0 + tx + 16 * y] =
                acc[x][y];
}

// ---------------------------------------------------------------------------
// convert M: sum 8 partials -> fp16 hi/lo
// ---------------------------------------------------------------------------
__global__ void convert_M() {
    int idx = blockIdx.x * blockDim.x + threadIdx.x;
    float v = 0.f;
#pragma unroll
    for (int p = 0; p < 8; p++) v += g_Mpart[p][idx];
    __half h = __float2half_rn(v);
    __half l = __float2half_rn(v - __half2float(h));
    g_Mh[idx] = h;
    g_Ml[idx] = l;
}

// ---------------------------------------------------------------------------
// Fused: logits GEMM (fp16 3-way split) + TWO-exchange cluster softmax
//        + W + ctx partials.
// Single-sync pipelined mainloop: per chunk, one __syncthreads; convert+STS
// of next chunk overlaps other warps' MMA of current chunk.
// grid (8, 2, 256): x = d-slice (cluster 8), y = b-half, z = i.
// ---------------------------------------------------------------------------
#define SA_OFF   0
#define SA_STAGE 20480   // hi 128*80 + lo 128*80
#define SA_HL    10240
#define SA_PITCH 80
#define SB_OFF   40960
#define SB_STAGE 17408   // hi 32*272 + lo 32*272
#define SB_HL    8704
#define SB_PITCH 272
#define RED_OFF   75776  // float[128][2]
#define RED1_OFF  76800  // float[8][128]
#define RED2_OFF  80896  // float[8][128]
#define GV_OFF    84992  // float[128]
#define INV_OFF   85504  // float[128]
#define CTXR_OFF  86016  // float[4][128]
#define SMEM_DYN  88064

__global__ void __cluster_dims__(8, 1, 1) __launch_bounds__(256, 2)
fused_attn(const float* __restrict__ FV, float* __restrict__ out) {
    extern __shared__ char smem[];
    const uint32_t sbase = smem_u32(smem);
    const int tid = threadIdx.x;
    const int lane = tid & 31, w = tid >> 5;
    const int i = blockIdx.z;
    const int bhalf = blockIdx.y;
    const int b0 = bhalf * 128;
    const int rank = blockIdx.x;
    const int d0 = rank * 128;
    const float* fvB = FV + (size_t)i * N_ * D_ + d0;                    // n-indexed
    const float* fvC = FV + (size_t)i * N_ * D_ + (size_t)b0 * D_ + d0;  // b-indexed

    float acc[2][8][4];
#pragma unroll
    for (int a = 0; a < 2; a++)
#pragma unroll
        for (int b = 0; b < 8; b++)
#pragma unroll
            for (int c = 0; c < 4; c++) acc[a][b][c] = 0.f;

    // A: threads 0-127 hi, 128-255 lo; one b-row (64B) x4 cp16
    const int ahl = tid >> 7;
    const int arow = tid & 127;
    const char* asrc = ahl ? (const char*)g_Ml : (const char*)g_Mh;
    auto loadA = [&](int c, int s) {
        uint32_t dst0 = sbase + SA_OFF + s * SA_STAGE + ahl * SA_HL + arow * SA_PITCH;
        const char* src = asrc + (size_t)(b0 + arow) * 512 + c * 64;
#pragma unroll
        for (int q = 0; q < 4; q++) cp16(dst0 + q * 16, src + q * 16);
        CP_COMMIT();
    };

    // B: chunk = 32 n-rows x 128 floats; 256 threads x 4 float4 (LDG prefetch)
    const int rk = tid >> 3;
    const int jb = (tid & 7) * 4;
    float4 bf[4];
    auto loadB = [&](int c) {
        const float4* src = (const float4*)(fvB + (size_t)(c * 32 + rk) * D_);
#pragma unroll
        for (int it = 0; it < 4; it++) bf[it] = src[(jb >> 2) + it * 8];
    };

    // convert bf (fp32) -> fp16 hi/lo, STS into stage s
    auto convB = [&](int s) {
        char* sbb = smem + SB_OFF + s * SB_STAGE + rk * SB_PITCH;
#pragma unroll
        for (int it = 0; it < 4; it++) {
            float4 v = bf[it];
            int j = jb + it * 32;
            __half hx = __float2half_rn(v.x), hy = __float2half_rn(v.y);
            __half hz = __float2half_rn(v.z), hw = __float2half_rn(v.w);
            __half2 p0 = __halves2half2(hx, hy), p1 = __halves2half2(hz, hw);
            uint2 hiw = make_uint2(*(uint32_t*)&p0, *(uint32_t*)&p1);
            __half lx = __float2half_rn(v.x - __half2float(hx));
            __half ly = __float2half_rn(v.y - __half2float(hy));
            __half lz = __float2half_rn(v.z - __half2float(hz));
            __half lw = __float2half_rn(v.w - __half2float(hw));
            __half2 q0 = __halves2half2(lx, ly), q1 = __halves2half2(lz, lw);
            uint2 low = make_uint2(*(uint32_t*)&q0, *(uint32_t*)&q1);
            *(uint2*)(sbb + j * 2) = hiw;
            *(uint2*)(sbb + SB_HL + j * 2) = low;
        }
    };

    // ---- prologue: stage 0 filled (A via cp.async, B via convert) ----
    loadB(0);                // bf = chunk 0
    loadA(0, 0);
    convB(0);                // stage 0 B ready (this thread)
    loadB(1);                // bf = chunk 1
    CP_WAIT0();              // A chunk 0 landed
    __syncthreads();         // stage 0 fully ready for all warps

    const int m0w = (w >> 1) * 32;
    const int n0w = (w & 1) * 64;
    const int kofB = (lane & 7) | (((lane >> 3) & 1) << 3);
    const int nofB = (lane >> 4) * 8;

#pragma unroll 1
    for (int c = 0; c < 8; c++) {
        const int s = c & 1;
        if (c < 7) loadA(c + 1, s ^ 1);   // cp.async overlaps this chunk's MMA

        const uint32_t sa_h = sbase + SA_OFF + s * SA_STAGE;
        const uint32_t sb_h = sbase + SB_OFF + s * SB_STAGE;
        const uint32_t aBase = sa_h + (m0w + (lane & 15)) * SA_PITCH + (lane >> 4) * 16;

#pragma unroll
        for (int ks = 0; ks < 2; ks++) {
            uint32_t aH[2][4], aL[2][4];
#pragma unroll
            for (int mf = 0; mf < 2; mf++) {
                uint32_t ad = aBase + mf * (16 * SA_PITCH) + ks * 32;
                ldsm_x4(aH[mf], ad);
                ldsm_x4(aL[mf], ad + SA_HL);
            }
#pragma unroll
            for (int nf2 = 0; nf2 < 4; nf2++) {
                uint32_t bad = sb_h + (ks * 16 + kofB) * SB_PITCH +
                               (n0w + nf2 * 16 + nofB) * 2;
                uint32_t bh[4], bl[4];
                ldsm_x4_t(bh, bad);
                ldsm_x4_t(bl, bad + SB_HL);
#pragma unroll
                for (int mf = 0; mf < 2; mf++) {
                    mma16816(acc[mf][2 * nf2],     aH[mf], bh);
                    mma16816(acc[mf][2 * nf2 + 1], aH[mf], bh + 2);
                    mma16816(acc[mf][2 * nf2],     aH[mf], bl);
                    mma16816(acc[mf][2 * nf2 + 1], aH[mf], bl + 2);
                    mma16816(acc[mf][2 * nf2],     aL[mf], bh);
                    mma16816(acc[mf][2 * nf2 + 1], aL[mf], bh + 2);
                }
            }
        }

        if (c < 7) {
            convB(s ^ 1);                 // bf holds chunk c+1; overlaps others' MMA
            if (c + 2 < 8) loadB(c + 2);  // prefetch chunk c+2 into bf
            CP_WAIT0();                   // A(c+1) landed (issued before MMA)
            __syncthreads();              // stage s^1 fully ready; stage s free
        }
    }

    // ---------------- R7 two-exchange softmax epilogue ----------------
    float* red  = (float*)(smem + RED_OFF);
    float* red1 = (float*)(smem + RED1_OFF);
    float* red2 = (float*)(smem + RED2_OFF);
    float* gv   = (float*)(smem + GV_OFF);
    float* inv  = (float*)(smem + INV_OFF);
    float* ctxr = (float*)(smem + CTXR_OFF);
    __syncthreads();

    float rmax[2][2];
#pragma unroll
    for (int mf = 0; mf < 2; mf++)
#pragma unroll
        for (int h = 0; h < 2; h++) {
            float m = -1e30f;
#pragma unroll
            for (int nf = 0; nf < 8; nf++)
                m = fmaxf(m, fmaxf(acc[mf][nf][2 * h], acc[mf][nf][2 * h + 1]));
            m = fmaxf(m, __shfl_xor_sync(0xffffffffu, m, 1));
            m = fmaxf(m, __shfl_xor_sync(0xffffffffu, m, 2));
            rmax[mf][h] = m;
        }
    if ((lane & 3) == 0) {
#pragma unroll
        for (int mf = 0; mf < 2; mf++)
#pragma unroll
            for (int h = 0; h < 2; h++) {
                int row = m0w + mf * 16 + (lane >> 2) + 8 * h;
                red[row * 2 + (w & 1)] = rmax[mf][h];
            }
    }
    __syncthreads();
    if (tid < 128) {
        float m = fmaxf(red[tid * 2], red[tid * 2 + 1]);
        const uint32_t a = sbase + RED1_OFF + (rank * 128 + tid) * 4;
#pragma unroll
        for (int p = 0; p < 8; p++) st_cluster_f32(a, p, m);
    }
    CLUSTER_ARV(); CLUSTER_WAIT();
    if (tid < 128) {
        float m = -1e30f;
#pragma unroll
        for (int p = 0; p < 8; p++) m = fmaxf(m, red1[p * 128 + tid]);
        gv[tid] = m;
    }
    __syncthreads();

    float rsum[2][2];
#pragma unroll
    for (int mf = 0; mf < 2; mf++)
#pragma unroll
        for (int h = 0; h < 2; h++) {
            int row = m0w + mf * 16 + (lane >> 2) + 8 * h;
            float gm = gv[row];
            float s = 0.f;
#pragma unroll
            for (int nf = 0; nf < 8; nf++) {
                float e0 = __expf(acc[mf][nf][2 * h] - gm);
                float e1 = __expf(acc[mf][nf][2 * h + 1] - gm);
                acc[mf][nf][2 * h] = e0;
                acc[mf][nf][2 * h + 1] = e1;
                s += e0 + e1;
            }
            s += __shfl_xor_sync(0xffffffffu, s, 1);
            s += __shfl_xor_sync(0xffffffffu, s, 2);
            rsum[mf][h] = s;
        }
    if ((lane & 3) == 0) {
#pragma unroll
        for (int mf = 0; mf < 2; mf++)
#pragma unroll
            for (int h = 0; h < 2; h++) {
                int row = m0w + mf * 16 + (lane >> 2) + 8 * h;
                red[row * 2 + (w & 1)] = rsum[mf][h];
            }
    }
    __syncthreads();
    if (tid < 128) {
        float s = red[tid * 2] + red[tid * 2 + 1];
        const uint32_t a = sbase + RED2_OFF + (rank * 128 + tid) * 4;
#pragma unroll
        for (int p = 0; p < 8; p++) st_cluster_f32(a, p, s);
    }
    CLUSTER_ARV(); CLUSTER_WAIT();
    if (tid < 128) {
        float s = 0.f;
#pragma unroll
        for (int p = 0; p < 8; p++) s += red2[p * 128 + tid];
        inv[tid] = __frcp_rn(s);
    }
    __syncthreads();

    // W write + ctx partial (b-indexed FV)
    float* Wout = out + (size_t)B_ * D_ + (size_t)i * N_ * D_ + (size_t)b0 * D_ + d0;
    float ctxc[16];
#pragma unroll
    for (int j = 0; j < 16; j++) ctxc[j] = 0.f;

#pragma unroll
    for (int mf = 0; mf < 2; mf++)
#pragma unroll
        for (int h = 0; h < 2; h++) {
            int row = m0w + mf * 16 + (lane >> 2) + 8 * h;
            float iv = inv[row];
            const float* fvr = fvC + (size_t)row * D_;
            float* wr = Wout + (size_t)row * D_;
#pragma unroll
            for (int nf = 0; nf < 8; nf++) {
                int col = n0w + nf * 8 + (lane & 3) * 2;
                float w0 = acc[mf][nf][2 * h] * iv;
                float w1 = acc[mf][nf][2 * h + 1] * iv;
                *(float2*)(wr + col) = make_float2(w0, w1);
                float2 f = *(const float2*)(fvr + col);
                ctxc[nf * 2]     = fmaf(w0, f.x, ctxc[nf * 2]);
                ctxc[nf * 2 + 1] = fmaf(w1, f.y, ctxc[nf * 2 + 1]);
            }
        }
#pragma unroll
    for (int j = 0; j < 16; j++) {
        ctxc[j] += __shfl_xor_sync(0xffffffffu, ctxc[j], 4);
        ctxc[j] += __shfl_xor_sync(0xffffffffu, ctxc[j], 8);
        ctxc[j] += __shfl_xor_sync(0xffffffffu, ctxc[j], 16);
    }
    if (lane < 4) {
#pragma unroll
        for (int nf = 0; nf < 8; nf++) {
            int col = n0w + nf * 8 + lane * 2;
            ctxr[(w >> 1) * 128 + col]     = ctxc[nf * 2];
            ctxr[(w >> 1) * 128 + col + 1] = ctxc[nf * 2 + 1];
        }
    }
    __syncthreads();
    if (tid < 128) {
        float s = 0.f;
#pragma unroll
        for (int p = 0; p < 4; p++) s += ctxr[p * 128 + tid];
        g_ctx[bhalf][(size_t)i * D_ + d0 + tid] = s;
    }
}

// ---------------------------------------------------------------------------
// final: out_ctx[i][d] = g_ctx[0][i][d] + g_ctx[1][i][d]
// ---------------------------------------------------------------------------
__global__ void ctx_reduce(float* __restrict__ out) {
    int idx = blockIdx.x * blockDim.x + threadIdx.x;
    const float4* a = (const float4*)g_ctx[0];
    const float4* b = (const float4*)g_ctx[1];
    float4 va = a[idx], vb = b[idx];
    ((float4*)out)[idx] = make_float4(va.x + vb.x, va.y + vb.y,
                                      va.z + vb.z, va.w + vb.w);
}

// ---------------------------------------------------------------------------
extern "C" void kernel_launch(void* const* d_in, const int* in_sizes, int n_in,
                              void* d_out, int out_size) {
    const float* FV    = (const float*)d_in[0];
    const float* state = (const float*)d_in[1];
    const float* Q     = (const float*)d_in[2];
    const float* Kmat  = (const float*)d_in[3];
    float* out = (float*)d_out;

    cudaFuncSetAttribute(fused_attn, cudaFuncAttributeMaxDynamicSharedMemorySize,
                         SMEM_DYN);

    gemm_nt_sk<<<dim3(S_ / 64, B_ / 64, 8), 256>>>(state, Q);
    gemm_nn_sk<<<dim3(N_ / 64, B_ / 64, 8), 256>>>(Kmat);
    convert_M<<<(B_ * N_) / 256, 256>>>();
    fused_attn<<<dim3(8, 2, B_), 256, SMEM_DYN>>>(FV, out);
    ctx_reduce<<<(B_ * D_ / 4) / 256, 256>>>(out);
}